// round 1
// baseline (speedup 1.0000x reference)
#include <cuda_runtime.h>
#include <cuda_bf16.h>

// OHEM loss, C=1 specialization:
//   ce == 0 exactly (logsumexp over singleton axis minus the same element),
//   so cls_loss == 0 and the hard-negative mining is dead code.
//   out = 0.2 * sum_{pos}(smoothL1(loc_preds - loc_targets)) / num_pos
//
// Pure HBM-bound masked reduction. cls_preds is never read.

#define NBLOCKS  1184   // 148 SMs * 8 blocks
#define NTHREADS 256
#define NWARPS   (NTHREADS / 32)

__device__ float g_partial_sum[NBLOCKS];
__device__ int   g_partial_cnt[NBLOCKS];

__device__ __forceinline__ float smooth_l1(float d) {
    float ax = fabsf(d);
    return (ax < 1.0f) ? 0.5f * d * d : ax - 0.5f;
}

__global__ __launch_bounds__(NTHREADS, 8)
void ohem_reduce_kernel(const float4* __restrict__ lp,   // loc_preds  as float4 (2 per anchor)
                        const float4* __restrict__ lt,   // loc_targets as float4
                        const int*    __restrict__ ct,   // cls_targets
                        int nAnchors)
{
    float sum = 0.0f;
    int   cnt = 0;

    const int stride = gridDim.x * blockDim.x;
    for (int i = blockIdx.x * blockDim.x + threadIdx.x; i < nAnchors; i += stride) {
        int t = ct[i];
        if (t > 0) {
            float4 p0 = lp[2 * i];
            float4 p1 = lp[2 * i + 1];
            float4 t0 = lt[2 * i];
            float4 t1 = lt[2 * i + 1];
            sum += smooth_l1(p0.x - t0.x);
            sum += smooth_l1(p0.y - t0.y);
            sum += smooth_l1(p0.z - t0.z);
            sum += smooth_l1(p0.w - t0.w);
            sum += smooth_l1(p1.x - t1.x);
            sum += smooth_l1(p1.y - t1.y);
            sum += smooth_l1(p1.z - t1.z);
            sum += smooth_l1(p1.w - t1.w);
            cnt++;
        }
    }

    // warp reduction
    #pragma unroll
    for (int off = 16; off > 0; off >>= 1) {
        sum += __shfl_xor_sync(0xFFFFFFFFu, sum, off);
        cnt += __shfl_xor_sync(0xFFFFFFFFu, cnt, off);
    }

    __shared__ float ssum[NWARPS];
    __shared__ int   scnt[NWARPS];
    int lane = threadIdx.x & 31;
    int wid  = threadIdx.x >> 5;
    if (lane == 0) { ssum[wid] = sum; scnt[wid] = cnt; }
    __syncthreads();

    if (wid == 0) {
        float s = (lane < NWARPS) ? ssum[lane] : 0.0f;
        int   c = (lane < NWARPS) ? scnt[lane] : 0;
        #pragma unroll
        for (int off = 16; off > 0; off >>= 1) {
            s += __shfl_xor_sync(0xFFFFFFFFu, s, off);
            c += __shfl_xor_sync(0xFFFFFFFFu, c, off);
        }
        if (lane == 0) {
            g_partial_sum[blockIdx.x] = s;
            g_partial_cnt[blockIdx.x] = c;
        }
    }
}

__global__ __launch_bounds__(NTHREADS)
void ohem_finalize_kernel(float* __restrict__ out)
{
    float sum = 0.0f;
    int   cnt = 0;
    for (int i = threadIdx.x; i < NBLOCKS; i += NTHREADS) {
        sum += g_partial_sum[i];
        cnt += g_partial_cnt[i];
    }
    #pragma unroll
    for (int off = 16; off > 0; off >>= 1) {
        sum += __shfl_xor_sync(0xFFFFFFFFu, sum, off);
        cnt += __shfl_xor_sync(0xFFFFFFFFu, cnt, off);
    }

    __shared__ float ssum[NWARPS];
    __shared__ int   scnt[NWARPS];
    int lane = threadIdx.x & 31;
    int wid  = threadIdx.x >> 5;
    if (lane == 0) { ssum[wid] = sum; scnt[wid] = cnt; }
    __syncthreads();

    if (wid == 0) {
        float s = (lane < NWARPS) ? ssum[lane] : 0.0f;
        int   c = (lane < NWARPS) ? scnt[lane] : 0;
        #pragma unroll
        for (int off = 16; off > 0; off >>= 1) {
            s += __shfl_xor_sync(0xFFFFFFFFu, s, off);
            c += __shfl_xor_sync(0xFFFFFFFFu, c, off);
        }
        if (lane == 0) {
            float N = (float)c;
            out[0] = 0.2f * s / N;   // cls_loss/N term is exactly 0 for C=1
        }
    }
}

extern "C" void kernel_launch(void* const* d_in, const int* in_sizes, int n_in,
                              void* d_out, int out_size)
{
    // metadata order: loc_preds [B,A,8] f32, loc_targets [B,A,8] f32,
    //                 cls_preds [B,A,1] f32 (UNUSED), cls_targets [B,A] i32
    const float4* lp = (const float4*)d_in[0];
    const float4* lt = (const float4*)d_in[1];
    const int*    ct = (const int*)d_in[3];
    float* out = (float*)d_out;

    int nAnchors = in_sizes[3];   // B*A = 3,200,000

    ohem_reduce_kernel<<<NBLOCKS, NTHREADS>>>(lp, lt, ct, nAnchors);
    ohem_finalize_kernel<<<1, NTHREADS>>>(out);
}